// round 11
// baseline (speedup 1.0000x reference)
#include <cuda_runtime.h>
#include <cstdint>
#include <cstddef>

#define HID   1024
#define NG    4096
#define BATCH 32
#define TT    512
#define NCTA  128

// ---------------- device scratch (allocation-free) ----------------
__device__ float g_xg[(size_t)TT * BATCH * NG];   // [t*32+b][4H] precomputed input gates
__device__ float g_xr[(size_t)TT * BATCH * HID];  // x, tf32-rounded, row m = t*32+b
__device__ float g_wr[(size_t)NG * HID];          // w_ih, tf32-rounded
__device__ float g_h[3][BATCH * HID];             // triple-buffered hidden state
__device__ unsigned g_flag[NCTA * 64];            // per-producer epoch flags, 256B apart

// ---------------- helpers ----------------
__device__ __forceinline__ float tf32r(float x) {
    unsigned u;
    asm("cvt.rna.tf32.f32 %0, %1;" : "=r"(u) : "f"(x));
    return __uint_as_float(u);
}

__device__ __forceinline__ void mma8(float* d, const unsigned* a, const unsigned* b) {
    asm volatile(
        "mma.sync.aligned.m16n8k8.row.col.f32.tf32.tf32.f32 "
        "{%0,%1,%2,%3}, {%4,%5,%6,%7}, {%8,%9}, {%0,%1,%2,%3};\n"
        : "+f"(d[0]), "+f"(d[1]), "+f"(d[2]), "+f"(d[3])
        : "r"(a[0]), "r"(a[1]), "r"(a[2]), "r"(a[3]), "r"(b[0]), "r"(b[1]));
}

__device__ __forceinline__ float sigm(float x) {
    return 1.f / (1.f + __expf(-x));
}

// saturating fast tanh: 1 - 2/(e^{2x}+1); e->inf => 1, e->0 => -1 (NaN-free)
__device__ __forceinline__ float ftanh(float x) {
    float e = __expf(2.f * x);
    return 1.f - 2.f / (e + 1.f);
}

// ---------------- fused prep: round to tf32; reorder x rows to m = t*32+b ----------------
__global__ void k_prep(const float4* __restrict__ x, const float4* __restrict__ w) {
    if (blockIdx.x < 16384) {
        size_t i = (size_t)blockIdx.x * 256 + threadIdx.x;
        int hq  = (int)(i & 255);
        int row = (int)(i >> 8);       // = b*512 + t
        int b   = row >> 9;
        int t   = row & 511;
        float4 v = x[i];
        v.x = tf32r(v.x); v.y = tf32r(v.y); v.z = tf32r(v.z); v.w = tf32r(v.w);
        ((float4*)g_xr)[((size_t)(t * 32 + b) << 8) + hq] = v;
    } else {
        size_t i = (size_t)(blockIdx.x - 16384) * 256 + threadIdx.x;  // over 1,048,576 float4
        float4 v = w[i];
        v.x = tf32r(v.x); v.y = tf32r(v.y); v.z = tf32r(v.z); v.w = tf32r(v.w);
        ((float4*)g_wr)[i] = v;
    }
}

// fused init: zero h buffer 0 + reset all flags
__global__ void k_init() {
    int i = blockIdx.x * 256 + threadIdx.x;   // 128 x 256 = 32768
    g_h[0][i] = 0.f;
    if (i < NCTA * 64) g_flag[i] = 0u;
}

// ---------------- Phase 1: xg = x' @ w_ih^T + b_ih + b_hh ----------------
// M=16384 (m = t*32+b), N=4096, K=1024. BM=128, BN=64, BK=32, 256 thr.
// Grid is n-FASTEST: blockIdx.x = n-block (64), blockIdx.y = m-block (128).
// Consecutive CTAs share the A m-tile via L2; all of w_ih (16 MB) stays
// L2-resident => A streamed from DRAM once.
// smem floats: A[2][128][36] then B[2][64][36]; pad 36 => conflict-free frag LDS.

__device__ __forceinline__ void p1_load(uint32_t sb, int s, int m0, int n0, int k0, int tid) {
    #pragma unroll
    for (int i = 0; i < 4; i++) {
        int ch = tid + i * 256;
        int row = ch >> 3, cq = ch & 7;
        uint32_t so = sb + (uint32_t)((s * 4608 + row * 36 + cq * 4) * 4);
        const float* gp = g_xr + (size_t)(m0 + row) * HID + k0 + cq * 4;
        asm volatile("cp.async.cg.shared.global [%0], [%1], 16;" :: "r"(so), "l"(gp));
    }
    #pragma unroll
    for (int i = 0; i < 2; i++) {
        int ch = tid + i * 256;
        int row = ch >> 3, cq = ch & 7;
        uint32_t so = sb + (uint32_t)((9216 + s * 2304 + row * 36 + cq * 4) * 4);
        const float* gp = g_wr + (size_t)(n0 + row) * HID + k0 + cq * 4;
        asm volatile("cp.async.cg.shared.global [%0], [%1], 16;" :: "r"(so), "l"(gp));
    }
    asm volatile("cp.async.commit_group;" ::: "memory");
}

__global__ void __launch_bounds__(256) k_gemm(const float* __restrict__ bih,
                                              const float* __restrict__ bhh) {
    extern __shared__ float sm[];
    const int tid  = threadIdx.x;
    const int lane = tid & 31, w = tid >> 5;
    const int wm = w >> 1, wn = w & 1;
    const int g = lane >> 2, tg = lane & 3;
    const int m0 = blockIdx.y * 128;   // n-fastest grid
    const int n0 = blockIdx.x * 64;
    uint32_t sb = (uint32_t)__cvta_generic_to_shared(sm);

    float acc[2][4][4];
    #pragma unroll
    for (int mt = 0; mt < 2; mt++)
        #pragma unroll
        for (int nt = 0; nt < 4; nt++)
            #pragma unroll
            for (int r = 0; r < 4; r++) acc[mt][nt][r] = 0.f;

    p1_load(sb, 0, m0, n0, 0, tid);
    int s = 0;
    for (int it = 0; it < 32; ++it) {
        if (it + 1 < 32) p1_load(sb, s ^ 1, m0, n0, (it + 1) * 32, tid);
        else asm volatile("cp.async.commit_group;" ::: "memory");
        asm volatile("cp.async.wait_group 1;" ::: "memory");
        __syncthreads();

        const unsigned* A = (const unsigned*)(sm + s * 4608);
        const unsigned* B = (const unsigned*)(sm + 9216 + s * 2304);
        #pragma unroll
        for (int ks = 0; ks < 4; ks++) {
            unsigned a[2][4], bf[4][2];
            #pragma unroll
            for (int mt = 0; mt < 2; mt++) {
                int r = wm * 32 + mt * 16 + g;
                int col = ks * 8 + tg;
                a[mt][0] = A[r * 36 + col];
                a[mt][1] = A[(r + 8) * 36 + col];
                a[mt][2] = A[r * 36 + col + 4];
                a[mt][3] = A[(r + 8) * 36 + col + 4];
            }
            #pragma unroll
            for (int nt = 0; nt < 4; nt++) {
                int r = wn * 32 + nt * 8 + g;
                int col = ks * 8 + tg;
                bf[nt][0] = B[r * 36 + col];
                bf[nt][1] = B[r * 36 + col + 4];
            }
            #pragma unroll
            for (int mt = 0; mt < 2; mt++)
                #pragma unroll
                for (int nt = 0; nt < 4; nt++)
                    mma8(acc[mt][nt], a[mt], bf[nt]);
        }
        __syncthreads();
        s ^= 1;
    }

    // epilogue: add biases, store to g_xg[m][n]
    #pragma unroll
    for (int mt = 0; mt < 2; mt++) {
        #pragma unroll
        for (int nt = 0; nt < 4; nt++) {
            int n = n0 + wn * 32 + nt * 8 + 2 * tg;
            float b0 = bih[n] + bhh[n];
            float b1 = bih[n + 1] + bhh[n + 1];
            int ma = m0 + wm * 32 + mt * 16 + g;
            float2 v0 = make_float2(acc[mt][nt][0] + b0, acc[mt][nt][1] + b1);
            float2 v1 = make_float2(acc[mt][nt][2] + b0, acc[mt][nt][3] + b1);
            *(float2*)&g_xg[(size_t)ma * NG + n]       = v0;
            *(float2*)&g_xg[(size_t)(ma + 8) * NG + n] = v1;
        }
    }
}

// ---------------- Phase 2: persistent recurrence (v6) ----------------
// 128 CTAs x 256 threads, 1 CTA/SM. CTA j owns hidden n0=j*8..j*8+7.
// w_hh fragments in REGISTERS. Per-producer epoch flags (no global barrier).
// Warp w consumes h columns [w*128, w*128+128) produced by CTAs w*16..w*16+15;
// lanes 0-15 ld.acquire-spin on those 16 flags, then warp-private cp.async
// staging (4 commit groups of 8 rows) overlapped with tf32 mma halves.
// h triple-buffered. Fast __expf-based tanh in the serial epilogue.
// smem floats: hbuf[8][32][132] (135168 B) then red[8][32][36] (36864 B).

#define P2_HALF(nt0)                                                        \
    _Pragma("unroll")                                                       \
    for (int ks = 0; ks < 16; ++ks) {                                       \
        int k0 = ks * 8 + tg;                                               \
        unsigned bf0[2], bf1[2];                                            \
        bf0[0] = hw[((nt0) * 8 + g) * 132 + k0];                            \
        bf0[1] = hw[((nt0) * 8 + g) * 132 + k0 + 4];                        \
        bf1[0] = hw[((nt0) * 8 + 8 + g) * 132 + k0];                        \
        bf1[1] = hw[((nt0) * 8 + 8 + g) * 132 + k0 + 4];                    \
        mma8(acc[0][(nt0)], a[ks][0], bf0);                                 \
        mma8(acc[1][(nt0)], a[ks][1], bf0);                                 \
        mma8(acc[0][(nt0) + 1], a[ks][0], bf1);                             \
        mma8(acc[1][(nt0) + 1], a[ks][1], bf1);                             \
    }

__global__ void __launch_bounds__(256) k_recur(const float* __restrict__ whh,
                                               float* __restrict__ out) {
    extern __shared__ float sm[];
    float* red = sm + 8 * 32 * 132;   // after per-warp h buffers
    const int tid  = threadIdx.x;
    const int lane = tid & 31, w = tid >> 5;
    const int g = lane >> 2, tg = lane & 3;
    const int n0 = blockIdx.x * 8;
    const int kw = w * 128;           // this warp's K slice
    const int j0 = w * 16;            // first producer CTA of this slice
    const int eb = tid >> 3;          // batch index for epilogue
    const int en = tid & 7;           // local hidden index for epilogue

    float* hbw = sm + w * 32 * 132;   // this warp's private h slice buffer
    uint32_t hb = (uint32_t)__cvta_generic_to_shared(hbw);
    const unsigned* hw = (const unsigned*)hbw;

    // Load this thread's w_hh A-fragments once; resident for all 512 steps.
    unsigned a[16][2][4];
    #pragma unroll
    for (int ks = 0; ks < 16; ks++) {
        #pragma unroll
        for (int mt = 0; mt < 2; mt++) {
            int r0 = mt * 16 + g;
            int r1 = r0 + 8;
            size_t row0 = (size_t)((r0 >> 3) * HID + n0 + (r0 & 7)) * HID;
            size_t row1 = (size_t)((r1 >> 3) * HID + n0 + (r1 & 7)) * HID;
            int k0 = kw + ks * 8 + tg;
            a[ks][mt][0] = __float_as_uint(tf32r(whh[row0 + k0]));
            a[ks][mt][1] = __float_as_uint(tf32r(whh[row1 + k0]));
            a[ks][mt][2] = __float_as_uint(tf32r(whh[row0 + k0 + 4]));
            a[ks][mt][3] = __float_as_uint(tf32r(whh[row1 + k0 + 4]));
        }
    }

    float c = 0.f;

    for (int t = 0; t < TT; ++t) {
        // prefetch input-gate values first (independent of flags; hides DRAM lat)
        const float* xp = g_xg + ((size_t)t * 32 + eb) * NG + n0 + en;
        float xi  = __ldcs(xp);
        float xf  = __ldcs(xp + 1024);
        float xgt = __ldcs(xp + 2048);
        float xo  = __ldcs(xp + 3072);

        // wait for this warp's 16 producers to publish h for step t
        if (lane < 16) {
            const unsigned* fp = g_flag + (j0 + lane) * 64;
            unsigned v;
            do {
                asm volatile("ld.acquire.gpu.global.u32 %0, [%1];"
                             : "=r"(v) : "l"(fp) : "memory");
            } while (v < (unsigned)t);
        }
        __syncwarp();

        const float* __restrict__ hcur = g_h[t % 3];

        // stage this warp's K-slice of h: 4 commit groups of 8 rows
        #pragma unroll
        for (int q = 0; q < 4; q++) {
            #pragma unroll
            for (int j = 0; j < 8; j++) {
                int r = q * 8 + j;
                uint32_t so = hb + (uint32_t)((r * 132 + lane * 4) * 4);
                const float* gp = hcur + r * HID + kw + lane * 4;
                asm volatile("cp.async.cg.shared.global [%0], [%1], 16;" :: "r"(so), "l"(gp));
            }
            asm volatile("cp.async.commit_group;" ::: "memory");
        }

        float acc[2][4][4];
        #pragma unroll
        for (int mt = 0; mt < 2; mt++)
            #pragma unroll
            for (int nt = 0; nt < 4; nt++)
                #pragma unroll
                for (int r = 0; r < 4; r++) acc[mt][nt][r] = 0.f;

        asm volatile("cp.async.wait_group 2;" ::: "memory");  // rows 0-15 ready
        __syncwarp();
        P2_HALF(0)
        asm volatile("cp.async.wait_group 0;" ::: "memory");  // rows 16-31 ready
        __syncwarp();
        P2_HALF(2)

        // D[r][b] partials -> smem (float2, pad 36)
        #pragma unroll
        for (int mt = 0; mt < 2; mt++) {
            #pragma unroll
            for (int nt = 0; nt < 4; nt++) {
                int r = mt * 16 + g, b = nt * 8 + 2 * tg;
                *(float2*)&red[(w * 32 + r) * 36 + b]     = make_float2(acc[mt][nt][0], acc[mt][nt][1]);
                *(float2*)&red[(w * 32 + r + 8) * 36 + b] = make_float2(acc[mt][nt][2], acc[mt][nt][3]);
            }
        }
        __syncthreads();

        // reduce 8 warps + cell update (thread -> (eb, en)); reads conflict-free
        float si = 0.f, sf = 0.f, sg = 0.f, so = 0.f;
        #pragma unroll
        for (int ww = 0; ww < 8; ww++) {
            si += red[(ww * 32 + en) * 36 + eb];
            sf += red[(ww * 32 + 8 + en) * 36 + eb];
            sg += red[(ww * 32 + 16 + en) * 36 + eb];
            so += red[(ww * 32 + 24 + en) * 36 + eb];
        }
        float gi = sigm(si + xi);
        float gf = sigm(sf + xf);
        float gg = ftanh(sg + xgt);
        float go = sigm(so + xo);
        c = gf * c + gi * gg;
        float h = go * ftanh(c);

        g_h[(t + 1) % 3][eb * HID + n0 + en] = tf32r(h);
        if (t == TT - 1) out[eb * HID + n0 + en] = h;

        // publish: all 256 h stores done -> one release store of this CTA's flag
        __syncthreads();
        if (tid == 0) {
            asm volatile("st.release.gpu.global.u32 [%0], %1;"
                         :: "l"(g_flag + blockIdx.x * 64), "r"((unsigned)(t + 1)) : "memory");
        }
    }
}

// ---------------- launch ----------------
extern "C" void kernel_launch(void* const* d_in, const int* in_sizes, int n_in,
                              void* d_out, int out_size) {
    const float* x   = (const float*)d_in[0];
    const float* wih = (const float*)d_in[1];
    const float* whh = (const float*)d_in[2];
    const float* bih = (const float*)d_in[3];
    const float* bhh = (const float*)d_in[4];
    float* out = (float*)d_out;

    cudaFuncSetAttribute(k_gemm,  cudaFuncAttributeMaxDynamicSharedMemorySize, 55296);
    cudaFuncSetAttribute(k_recur, cudaFuncAttributeMaxDynamicSharedMemorySize, 172032);

    k_prep<<<20480, 256>>>((const float4*)x, (const float4*)wih);
    k_init<<<128, 256>>>();

    dim3 gg(64, 128);   // n-fastest
    k_gemm<<<gg, 256, 55296>>>(bih, bhh);
    k_recur<<<NCTA, 256, 172032>>>(whh, out);
}

// round 12
// speedup vs baseline: 1.2195x; 1.2195x over previous
#include <cuda_runtime.h>
#include <cuda_fp16.h>
#include <cstdint>
#include <cstddef>

#define HID   1024
#define NG    4096
#define BATCH 32
#define TT    512
#define NCTA  128

// ---------------- device scratch (allocation-free) ----------------
__device__ float  g_xg[(size_t)TT * BATCH * NG];   // [t*32+b][4H] precomputed input gates
__device__ float  g_xr[(size_t)TT * BATCH * HID];  // x, tf32-rounded, row m = t*32+b
__device__ float  g_wr[(size_t)NG * HID];          // w_ih, tf32-rounded
__device__ __half g_hh[3][BATCH * HID];            // triple-buffered hidden state (fp16)
__device__ unsigned g_flag[NCTA * 64];             // per-producer epoch flags, 256B apart

// ---------------- helpers ----------------
__device__ __forceinline__ float tf32r(float x) {
    unsigned u;
    asm("cvt.rna.tf32.f32 %0, %1;" : "=r"(u) : "f"(x));
    return __uint_as_float(u);
}

// tf32 mma (phase 1)
__device__ __forceinline__ void mma8(float* d, const unsigned* a, const unsigned* b) {
    asm volatile(
        "mma.sync.aligned.m16n8k8.row.col.f32.tf32.tf32.f32 "
        "{%0,%1,%2,%3}, {%4,%5,%6,%7}, {%8,%9}, {%0,%1,%2,%3};\n"
        : "+f"(d[0]), "+f"(d[1]), "+f"(d[2]), "+f"(d[3])
        : "r"(a[0]), "r"(a[1]), "r"(a[2]), "r"(a[3]), "r"(b[0]), "r"(b[1]));
}

// fp16 mma, fp32 accumulate (phase 2)
__device__ __forceinline__ void mma16(float* d, const unsigned* a, unsigned b0, unsigned b1) {
    asm volatile(
        "mma.sync.aligned.m16n8k16.row.col.f32.f16.f16.f32 "
        "{%0,%1,%2,%3}, {%4,%5,%6,%7}, {%8,%9}, {%0,%1,%2,%3};\n"
        : "+f"(d[0]), "+f"(d[1]), "+f"(d[2]), "+f"(d[3])
        : "r"(a[0]), "r"(a[1]), "r"(a[2]), "r"(a[3]), "r"(b0), "r"(b1));
}

__device__ __forceinline__ unsigned packh(float lo, float hi) {
    __half2 h = __floats2half2_rn(lo, hi);
    return *(unsigned*)&h;
}

__device__ __forceinline__ float sigm(float x) {
    return 1.f / (1.f + __expf(-x));
}

// saturating fast tanh: 1 - 2/(e^{2x}+1); NaN-free at +-inf
__device__ __forceinline__ float ftanh(float x) {
    float e = __expf(2.f * x);
    return 1.f - 2.f / (e + 1.f);
}

// ---------------- fused prep: round to tf32; reorder x rows to m = t*32+b ----------------
__global__ void k_prep(const float4* __restrict__ x, const float4* __restrict__ w) {
    if (blockIdx.x < 16384) {
        size_t i = (size_t)blockIdx.x * 256 + threadIdx.x;
        int hq  = (int)(i & 255);
        int row = (int)(i >> 8);       // = b*512 + t
        int b   = row >> 9;
        int t   = row & 511;
        float4 v = x[i];
        v.x = tf32r(v.x); v.y = tf32r(v.y); v.z = tf32r(v.z); v.w = tf32r(v.w);
        ((float4*)g_xr)[((size_t)(t * 32 + b) << 8) + hq] = v;
    } else {
        size_t i = (size_t)(blockIdx.x - 16384) * 256 + threadIdx.x;  // over 1,048,576 float4
        float4 v = w[i];
        v.x = tf32r(v.x); v.y = tf32r(v.y); v.z = tf32r(v.z); v.w = tf32r(v.w);
        ((float4*)g_wr)[i] = v;
    }
}

// fused init: zero h buffer 0 + reset all flags
__global__ void k_init() {
    int i = blockIdx.x * 256 + threadIdx.x;   // 128 x 256 = 32768
    g_hh[0][i] = __float2half(0.f);
    if (i < NCTA * 64) g_flag[i] = 0u;
}

// ---------------- Phase 1: xg = x' @ w_ih^T + b_ih + b_hh (tf32) ----------------
// M=16384 (m = t*32+b), N=4096, K=1024. BM=128, BN=64, BK=32, 256 thr.
// m-fastest grid (R10 showed n-fastest was not better; A+B stay L2-resident).
// smem floats: A[2][128][36] then B[2][64][36]; pad 36 => conflict-free frag LDS.

__device__ __forceinline__ void p1_load(uint32_t sb, int s, int m0, int n0, int k0, int tid) {
    #pragma unroll
    for (int i = 0; i < 4; i++) {
        int ch = tid + i * 256;
        int row = ch >> 3, cq = ch & 7;
        uint32_t so = sb + (uint32_t)((s * 4608 + row * 36 + cq * 4) * 4);
        const float* gp = g_xr + (size_t)(m0 + row) * HID + k0 + cq * 4;
        asm volatile("cp.async.cg.shared.global [%0], [%1], 16;" :: "r"(so), "l"(gp));
    }
    #pragma unroll
    for (int i = 0; i < 2; i++) {
        int ch = tid + i * 256;
        int row = ch >> 3, cq = ch & 7;
        uint32_t so = sb + (uint32_t)((9216 + s * 2304 + row * 36 + cq * 4) * 4);
        const float* gp = g_wr + (size_t)(n0 + row) * HID + k0 + cq * 4;
        asm volatile("cp.async.cg.shared.global [%0], [%1], 16;" :: "r"(so), "l"(gp));
    }
    asm volatile("cp.async.commit_group;" ::: "memory");
}

__global__ void __launch_bounds__(256) k_gemm(const float* __restrict__ bih,
                                              const float* __restrict__ bhh) {
    extern __shared__ float sm[];
    const int tid  = threadIdx.x;
    const int lane = tid & 31, w = tid >> 5;
    const int wm = w >> 1, wn = w & 1;
    const int g = lane >> 2, tg = lane & 3;
    const int m0 = blockIdx.x * 128;
    const int n0 = blockIdx.y * 64;
    uint32_t sb = (uint32_t)__cvta_generic_to_shared(sm);

    float acc[2][4][4];
    #pragma unroll
    for (int mt = 0; mt < 2; mt++)
        #pragma unroll
        for (int nt = 0; nt < 4; nt++)
            #pragma unroll
            for (int r = 0; r < 4; r++) acc[mt][nt][r] = 0.f;

    p1_load(sb, 0, m0, n0, 0, tid);
    int s = 0;
    for (int it = 0; it < 32; ++it) {
        if (it + 1 < 32) p1_load(sb, s ^ 1, m0, n0, (it + 1) * 32, tid);
        else asm volatile("cp.async.commit_group;" ::: "memory");
        asm volatile("cp.async.wait_group 1;" ::: "memory");
        __syncthreads();

        const unsigned* A = (const unsigned*)(sm + s * 4608);
        const unsigned* B = (const unsigned*)(sm + 9216 + s * 2304);
        #pragma unroll
        for (int ks = 0; ks < 4; ks++) {
            unsigned a[2][4], bf[4][2];
            #pragma unroll
            for (int mt = 0; mt < 2; mt++) {
                int r = wm * 32 + mt * 16 + g;
                int col = ks * 8 + tg;
                a[mt][0] = A[r * 36 + col];
                a[mt][1] = A[(r + 8) * 36 + col];
                a[mt][2] = A[r * 36 + col + 4];
                a[mt][3] = A[(r + 8) * 36 + col + 4];
            }
            #pragma unroll
            for (int nt = 0; nt < 4; nt++) {
                int r = wn * 32 + nt * 8 + g;
                int col = ks * 8 + tg;
                bf[nt][0] = B[r * 36 + col];
                bf[nt][1] = B[r * 36 + col + 4];
            }
            #pragma unroll
            for (int mt = 0; mt < 2; mt++)
                #pragma unroll
                for (int nt = 0; nt < 4; nt++)
                    mma8(acc[mt][nt], a[mt], bf[nt]);
        }
        __syncthreads();
        s ^= 1;
    }

    // epilogue: add biases, store to g_xg[m][n]
    #pragma unroll
    for (int mt = 0; mt < 2; mt++) {
        #pragma unroll
        for (int nt = 0; nt < 4; nt++) {
            int n = n0 + wn * 32 + nt * 8 + 2 * tg;
            float b0 = bih[n] + bhh[n];
            float b1 = bih[n + 1] + bhh[n + 1];
            int ma = m0 + wm * 32 + mt * 16 + g;
            float2 v0 = make_float2(acc[mt][nt][0] + b0, acc[mt][nt][1] + b1);
            float2 v1 = make_float2(acc[mt][nt][2] + b0, acc[mt][nt][3] + b1);
            *(float2*)&g_xg[(size_t)ma * NG + n]       = v0;
            *(float2*)&g_xg[(size_t)(ma + 8) * NG + n] = v1;
        }
    }
}

// ---------------- Phase 2: persistent recurrence (v7, fp16 mma) ----------------
// 128 CTAs x 256 threads, 1 CTA/SM. CTA j owns hidden n0=j*8..j*8+7.
// h stored fp16 (11-bit mantissa == tf32): halves staging traffic AND mma count.
// w_hh fp16 A-fragments in REGISTERS (a[8][2][4]). Per-producer epoch flags.
// Warp w consumes h cols [w*128,(w+1)*128) (fp16), staged warp-privately via
// cp.async in 2 commit groups of 16 batch-rows; mma m16n8k16 overlaps group 2.
// smem row stride 136 halves (68 words == 4 mod 32) => conflict-free frag LDS.
// smem: hbuf 8*32*68 words (69632 B) then red[8][32][36] floats (36864 B).

#define P2H(nt0)                                                            \
    _Pragma("unroll")                                                       \
    for (int ks = 0; ks < 8; ++ks) {                                        \
        int k0 = ks * 8 + tg;                                               \
        unsigned b00 = hwu[((nt0) * 8 + g) * 68 + k0];                      \
        unsigned b01 = hwu[((nt0) * 8 + g) * 68 + k0 + 4];                  \
        unsigned b10 = hwu[((nt0) * 8 + 8 + g) * 68 + k0];                  \
        unsigned b11 = hwu[((nt0) * 8 + 8 + g) * 68 + k0 + 4];              \
        mma16(acc[0][(nt0)], a[ks][0], b00, b01);                           \
        mma16(acc[1][(nt0)], a[ks][1], b00, b01);                           \
        mma16(acc[0][(nt0) + 1], a[ks][0], b10, b11);                       \
        mma16(acc[1][(nt0) + 1], a[ks][1], b10, b11);                       \
    }

__global__ void __launch_bounds__(256) k_recur(const float* __restrict__ whh,
                                               float* __restrict__ out) {
    extern __shared__ float sm[];
    float* red = sm + 17408;          // after 8 * 2176-word h buffers
    const int tid  = threadIdx.x;
    const int lane = tid & 31, w = tid >> 5;
    const int g = lane >> 2, tg = lane & 3;
    const int n0 = blockIdx.x * 8;
    const int kw = w * 128;           // this warp's hidden (K) slice
    const int j0 = w * 16;            // first producer CTA of this slice
    const int eb = tid >> 3;          // batch index for epilogue
    const int en = tid & 7;           // local hidden index for epilogue

    unsigned* hwu = (unsigned*)sm + w * 2176;  // warp-private h slice (32 x 68 words)
    uint32_t hb = (uint32_t)__cvta_generic_to_shared(hwu);

    // Load this thread's w_hh A-fragments (fp16 pairs) once; resident all steps.
    // local row r = gate*8 + unit -> global row (r>>3)*HID + n0 + (r&7)
    unsigned a[8][2][4];
    #pragma unroll
    for (int ks = 0; ks < 8; ks++) {
        #pragma unroll
        for (int mt = 0; mt < 2; mt++) {
            int r0 = mt * 16 + g;
            int r1 = r0 + 8;
            const float* row0 = whh + (size_t)((r0 >> 3) * HID + n0 + (r0 & 7)) * HID;
            const float* row1 = whh + (size_t)((r1 >> 3) * HID + n0 + (r1 & 7)) * HID;
            int kb = kw + ks * 16 + 2 * tg;
            a[ks][mt][0] = packh(row0[kb],     row0[kb + 1]);
            a[ks][mt][1] = packh(row1[kb],     row1[kb + 1]);
            a[ks][mt][2] = packh(row0[kb + 8], row0[kb + 9]);
            a[ks][mt][3] = packh(row1[kb + 8], row1[kb + 9]);
        }
    }

    float c = 0.f;

    for (int t = 0; t < TT; ++t) {
        // prefetch input-gate values first (independent of flags; hides DRAM lat)
        const float* xp = g_xg + ((size_t)t * 32 + eb) * NG + n0 + en;
        float xi  = __ldcs(xp);
        float xf  = __ldcs(xp + 1024);
        float xgt = __ldcs(xp + 2048);
        float xo  = __ldcs(xp + 3072);

        // wait for this warp's 16 producers to publish h for step t
        if (lane < 16) {
            const unsigned* fp = g_flag + (j0 + lane) * 64;
            unsigned v;
            do {
                asm volatile("ld.acquire.gpu.global.u32 %0, [%1];"
                             : "=r"(v) : "l"(fp) : "memory");
            } while (v < (unsigned)t);
        }
        __syncwarp();

        const __half* __restrict__ hsrc = g_hh[t % 3];

        // stage this warp's K-slice of h (fp16): 2 commit groups of 16 rows.
        // per iter: 2 rows x 16 chunks of 16B; lane -> row 2i+(lane>>4), chunk lane&15
        #pragma unroll
        for (int half = 0; half < 2; half++) {
            #pragma unroll
            for (int i = 0; i < 8; i++) {
                int r = half * 16 + i * 2 + (lane >> 4);
                int cch = lane & 15;
                uint32_t so = hb + (uint32_t)((r * 68 + cch * 4) * 4);
                const __half* gp = hsrc + r * HID + kw + cch * 8;
                asm volatile("cp.async.cg.shared.global [%0], [%1], 16;" :: "r"(so), "l"(gp));
            }
            asm volatile("cp.async.commit_group;" ::: "memory");
        }

        float acc[2][4][4];
        #pragma unroll
        for (int mt = 0; mt < 2; mt++)
            #pragma unroll
            for (int nt = 0; nt < 4; nt++)
                #pragma unroll
                for (int r = 0; r < 4; r++) acc[mt][nt][r] = 0.f;

        asm volatile("cp.async.wait_group 1;" ::: "memory");  // rows 0-15 ready
        __syncwarp();
        P2H(0)
        asm volatile("cp.async.wait_group 0;" ::: "memory");  // rows 16-31 ready
        __syncwarp();
        P2H(2)

        // D[r][b] partials -> smem (float2, pad 36)
        #pragma unroll
        for (int mt = 0; mt < 2; mt++) {
            #pragma unroll
            for (int nt = 0; nt < 4; nt++) {
                int r = mt * 16 + g, b = nt * 8 + 2 * tg;
                *(float2*)&red[(w * 32 + r) * 36 + b]     = make_float2(acc[mt][nt][0], acc[mt][nt][1]);
                *(float2*)&red[(w * 32 + r + 8) * 36 + b] = make_float2(acc[mt][nt][2], acc[mt][nt][3]);
            }
        }
        __syncthreads();

        // reduce 8 warps + cell update (thread -> (eb, en)); reads conflict-free
        float si = 0.f, sf = 0.f, sg = 0.f, so = 0.f;
        #pragma unroll
        for (int ww = 0; ww < 8; ww++) {
            si += red[(ww * 32 + en) * 36 + eb];
            sf += red[(ww * 32 + 8 + en) * 36 + eb];
            sg += red[(ww * 32 + 16 + en) * 36 + eb];
            so += red[(ww * 32 + 24 + en) * 36 + eb];
        }
        float gi = sigm(si + xi);
        float gf = sigm(sf + xf);
        float gg = ftanh(sg + xgt);
        float go = sigm(so + xo);
        c = gf * c + gi * gg;
        float h = go * ftanh(c);

        g_hh[(t + 1) % 3][eb * HID + n0 + en] = __float2half(h);
        if (t == TT - 1) out[eb * HID + n0 + en] = h;

        // publish: all 256 h stores done -> one release store of this CTA's flag
        __syncthreads();
        if (tid == 0) {
            asm volatile("st.release.gpu.global.u32 [%0], %1;"
                         :: "l"(g_flag + blockIdx.x * 64), "r"((unsigned)(t + 1)) : "memory");
        }
    }
}

// ---------------- launch ----------------
extern "C" void kernel_launch(void* const* d_in, const int* in_sizes, int n_in,
                              void* d_out, int out_size) {
    const float* x   = (const float*)d_in[0];
    const float* wih = (const float*)d_in[1];
    const float* whh = (const float*)d_in[2];
    const float* bih = (const float*)d_in[3];
    const float* bhh = (const float*)d_in[4];
    float* out = (float*)d_out;

    cudaFuncSetAttribute(k_gemm,  cudaFuncAttributeMaxDynamicSharedMemorySize, 55296);
    cudaFuncSetAttribute(k_recur, cudaFuncAttributeMaxDynamicSharedMemorySize, 106496);

    k_prep<<<20480, 256>>>((const float4*)x, (const float4*)wih);
    k_init<<<128, 256>>>();

    dim3 gg(128, 64);   // m-fastest (reverted)
    k_gemm<<<gg, 256, 55296>>>(bih, bhh);
    k_recur<<<NCTA, 256, 106496>>>(whh, out);
}

// round 16
// speedup vs baseline: 1.4983x; 1.2286x over previous
#include <cuda_runtime.h>
#include <cuda_fp16.h>
#include <cstdint>
#include <cstddef>

#define HID   1024
#define NG    4096
#define BATCH 32
#define TT    512
#define NCTA  128

// ---------------- device scratch (allocation-free) ----------------
__device__ float  g_xg[(size_t)TT * BATCH * NG];   // [t*32+b][4H] precomputed input gates (fp32)
__device__ __half g_xh[(size_t)TT * BATCH * HID];  // x, fp16, row m = t*32+b
__device__ __half g_wh[(size_t)NG * HID];          // w_ih, fp16
__device__ __half g_hh[3][BATCH * HID];            // triple-buffered hidden state (fp16)
__device__ unsigned g_flag[NCTA * 64];             // per-producer epoch flags, 256B apart

// ---------------- helpers ----------------
// fp16 mma, fp32 accumulate
__device__ __forceinline__ void mma16(float* d, const unsigned* a, unsigned b0, unsigned b1) {
    asm volatile(
        "mma.sync.aligned.m16n8k16.row.col.f32.f16.f16.f32 "
        "{%0,%1,%2,%3}, {%4,%5,%6,%7}, {%8,%9}, {%0,%1,%2,%3};\n"
        : "+f"(d[0]), "+f"(d[1]), "+f"(d[2]), "+f"(d[3])
        : "r"(a[0]), "r"(a[1]), "r"(a[2]), "r"(a[3]), "r"(b0), "r"(b1));
}

__device__ __forceinline__ unsigned packh(float lo, float hi) {
    __half2 h = __floats2half2_rn(lo, hi);
    return *(unsigned*)&h;
}

__device__ __forceinline__ float sigm(float x) {
    float e = __expf(-x);
    return __fdividef(1.f, 1.f + e);     // rcp(inf)=0 -> saturates correctly
}

// saturating fast tanh: 1 - 2/(e^{2x}+1); NaN-free at +-inf
__device__ __forceinline__ float ftanh(float x) {
    float e = __expf(2.f * x);
    return 1.f - __fdividef(2.f, e + 1.f);
}

// ---------------- fused prep: convert to fp16; reorder x rows to m = t*32+b ----------------
__global__ void k_prep(const float4* __restrict__ x, const float4* __restrict__ w) {
    if (blockIdx.x < 16384) {
        size_t i = (size_t)blockIdx.x * 256 + threadIdx.x;  // over 4,194,304 float4
        int hq  = (int)(i & 255);
        int row = (int)(i >> 8);       // = b*512 + t
        int b   = row >> 9;
        int t   = row & 511;
        float4 v = x[i];
        uint2 p = make_uint2(packh(v.x, v.y), packh(v.z, v.w));
        ((uint2*)g_xh)[(size_t)(t * 32 + b) * 256 + hq] = p;
    } else {
        size_t i = (size_t)(blockIdx.x - 16384) * 256 + threadIdx.x;  // over 1,048,576 float4
        float4 v = w[i];
        uint2 p = make_uint2(packh(v.x, v.y), packh(v.z, v.w));
        ((uint2*)g_wh)[i] = p;
    }
}

// fused init: zero h buffer 0 + reset all flags
__global__ void k_init() {
    int i = blockIdx.x * 256 + threadIdx.x;   // 128 x 256 = 32768
    g_hh[0][i] = __float2half(0.f);
    if (i < NCTA * 64) g_flag[i] = 0u;
}

// ---------------- Phase 1: xg = x' @ w_ih^T + b_ih + b_hh (fp16 mma) ----------------
// M=16384 (m = t*32+b), N=4096, K=1024. BM=128, BN=64, BK=64 halves, 256 thr.
// smem layout (words): A[2][128][36] then B[2][64][36]  (row = 64 halves + pad
// to 72 => stride 36 words; frag LDS bank = 4g+tg+8ks -> conflict-free).
// Per k-iter: 4 mma-k steps of 16. 16 iterations total.

__device__ __forceinline__ void p1_load(uint32_t sb, int s, int m0, int n0, int k0, int tid) {
    #pragma unroll
    for (int i = 0; i < 4; i++) {
        int ch = tid + i * 256;                // 1024 chunks: 128 rows x 8
        int row = ch >> 3, cq = ch & 7;
        uint32_t so = sb + (uint32_t)((s * 4608 + row * 36 + cq * 4) * 4);
        const __half* gp = g_xh + (size_t)(m0 + row) * HID + k0 + cq * 8;
        asm volatile("cp.async.cg.shared.global [%0], [%1], 16;" :: "r"(so), "l"(gp));
    }
    #pragma unroll
    for (int i = 0; i < 2; i++) {
        int ch = tid + i * 256;                // 512 chunks: 64 rows x 8
        int row = ch >> 3, cq = ch & 7;
        uint32_t so = sb + (uint32_t)((9216 + s * 2304 + row * 36 + cq * 4) * 4);
        const __half* gp = g_wh + (size_t)(n0 + row) * HID + k0 + cq * 8;
        asm volatile("cp.async.cg.shared.global [%0], [%1], 16;" :: "r"(so), "l"(gp));
    }
    asm volatile("cp.async.commit_group;" ::: "memory");
}

__global__ void __launch_bounds__(256) k_gemm(const float* __restrict__ bih,
                                              const float* __restrict__ bhh) {
    extern __shared__ float sm[];
    const int tid  = threadIdx.x;
    const int lane = tid & 31, w = tid >> 5;
    const int wm = w >> 1, wn = w & 1;
    const int g = lane >> 2, tg = lane & 3;
    const int m0 = blockIdx.x * 128;
    const int n0 = blockIdx.y * 64;
    uint32_t sb = (uint32_t)__cvta_generic_to_shared(sm);

    float acc[2][4][4];
    #pragma unroll
    for (int mt = 0; mt < 2; mt++)
        #pragma unroll
        for (int nt = 0; nt < 4; nt++)
            #pragma unroll
            for (int r = 0; r < 4; r++) acc[mt][nt][r] = 0.f;

    p1_load(sb, 0, m0, n0, 0, tid);
    int s = 0;
    for (int it = 0; it < 16; ++it) {
        if (it + 1 < 16) p1_load(sb, s ^ 1, m0, n0, (it + 1) * 64, tid);
        else asm volatile("cp.async.commit_group;" ::: "memory");
        asm volatile("cp.async.wait_group 1;" ::: "memory");
        __syncthreads();

        const unsigned* A = (const unsigned*)(sm + s * 4608);
        const unsigned* B = (const unsigned*)(sm + 9216 + s * 2304);
        #pragma unroll
        for (int ks = 0; ks < 4; ks++) {
            int col = ks * 8 + tg;
            unsigned a[2][4];
            #pragma unroll
            for (int mt = 0; mt < 2; mt++) {
                int r = wm * 32 + mt * 16 + g;
                a[mt][0] = A[r * 36 + col];
                a[mt][1] = A[(r + 8) * 36 + col];
                a[mt][2] = A[r * 36 + col + 4];
                a[mt][3] = A[(r + 8) * 36 + col + 4];
            }
            #pragma unroll
            for (int nt = 0; nt < 4; nt++) {
                int r = wn * 32 + nt * 8 + g;
                unsigned b0 = B[r * 36 + col];
                unsigned b1 = B[r * 36 + col + 4];
                mma16(acc[0][nt], a[0], b0, b1);
                mma16(acc[1][nt], a[1], b0, b1);
            }
        }
        __syncthreads();
        s ^= 1;
    }

    // epilogue: add biases, store to g_xg[m][n] (fp32)
    #pragma unroll
    for (int mt = 0; mt < 2; mt++) {
        #pragma unroll
        for (int nt = 0; nt < 4; nt++) {
            int n = n0 + wn * 32 + nt * 8 + 2 * tg;
            float b0 = bih[n] + bhh[n];
            float b1 = bih[n + 1] + bhh[n + 1];
            int ma = m0 + wm * 32 + mt * 16 + g;
            float2 v0 = make_float2(acc[mt][nt][0] + b0, acc[mt][nt][1] + b1);
            float2 v1 = make_float2(acc[mt][nt][2] + b0, acc[mt][nt][3] + b1);
            *(float2*)&g_xg[(size_t)ma * NG + n]       = v0;
            *(float2*)&g_xg[(size_t)(ma + 8) * NG + n] = v1;
        }
    }
}

// ---------------- Phase 2: persistent recurrence (fp16 mma, v7) ----------------
// 128 CTAs x 256 threads, 1 CTA/SM. CTA j owns hidden n0=j*8..j*8+7.
// h stored fp16; w_hh fp16 A-fragments in REGISTERS (a[8][2][4]).
// Per-producer epoch flags (no global barrier). Warp w consumes h cols
// [w*128,(w+1)*128), staged warp-privately via cp.async in 2 commit groups of
// 16 batch-rows; mma m16n8k16 overlaps group 2. Row stride 68 words.
// smem: hbuf 8*32*68 words (69632 B) then red[8][32][36] floats (36864 B).

#define P2H(nt0)                                                            \
    _Pragma("unroll")                                                       \
    for (int ks = 0; ks < 8; ++ks) {                                        \
        int k0 = ks * 8 + tg;                                               \
        unsigned b00 = hwu[((nt0) * 8 + g) * 68 + k0];                      \
        unsigned b01 = hwu[((nt0) * 8 + g) * 68 + k0 + 4];                  \
        unsigned b10 = hwu[((nt0) * 8 + 8 + g) * 68 + k0];                  \
        unsigned b11 = hwu[((nt0) * 8 + 8 + g) * 68 + k0 + 4];              \
        mma16(acc[0][(nt0)], a[ks][0], b00, b01);                           \
        mma16(acc[1][(nt0)], a[ks][1], b00, b01);                           \
        mma16(acc[0][(nt0) + 1], a[ks][0], b10, b11);                       \
        mma16(acc[1][(nt0) + 1], a[ks][1], b10, b11);                       \
    }

__global__ void __launch_bounds__(256) k_recur(const float* __restrict__ whh,
                                               float* __restrict__ out) {
    extern __shared__ float sm[];
    float* red = sm + 17408;          // after 8 * 2176-word h buffers
    const int tid  = threadIdx.x;
    const int lane = tid & 31, w = tid >> 5;
    const int g = lane >> 2, tg = lane & 3;
    const int n0 = blockIdx.x * 8;
    const int kw = w * 128;           // this warp's hidden (K) slice
    const int j0 = w * 16;            // first producer CTA of this slice
    const int eb = tid >> 3;          // batch index for epilogue
    const int en = tid & 7;           // local hidden index for epilogue

    unsigned* hwu = (unsigned*)sm + w * 2176;  // warp-private h slice (32 x 68 words)
    uint32_t hb = (uint32_t)__cvta_generic_to_shared(hwu);

    // Load this thread's w_hh A-fragments (fp16 pairs) once; resident all steps.
    // local row r = gate*8 + unit -> global row (r>>3)*HID + n0 + (r&7)
    unsigned a[8][2][4];
    #pragma unroll
    for (int ks = 0; ks < 8; ks++) {
        #pragma unroll
        for (int mt = 0; mt < 2; mt++) {
            int r0 = mt * 16 + g;
            int r1 = r0 + 8;
            const float* row0 = whh + (size_t)((r0 >> 3) * HID + n0 + (r0 & 7)) * HID;
            const float* row1 = whh + (size_t)((r1 >> 3) * HID + n0 + (r1 & 7)) * HID;
            int kb = kw + ks * 16 + 2 * tg;
            a[ks][mt][0] = packh(row0[kb],     row0[kb + 1]);
            a[ks][mt][1] = packh(row1[kb],     row1[kb + 1]);
            a[ks][mt][2] = packh(row0[kb + 8], row0[kb + 9]);
            a[ks][mt][3] = packh(row1[kb + 8], row1[kb + 9]);
        }
    }

    float c = 0.f;

    for (int t = 0; t < TT; ++t) {
        // prefetch input-gate values first (independent of flags; hides DRAM lat)
        const float* xp = g_xg + ((size_t)t * 32 + eb) * NG + n0 + en;
        float xi  = __ldcs(xp);
        float xf  = __ldcs(xp + 1024);
        float xgt = __ldcs(xp + 2048);
        float xo  = __ldcs(xp + 3072);

        // wait for this warp's 16 producers to publish h for step t
        if (lane < 16) {
            const unsigned* fp = g_flag + (j0 + lane) * 64;
            unsigned v;
            do {
                asm volatile("ld.acquire.gpu.global.u32 %0, [%1];"
                             : "=r"(v) : "l"(fp) : "memory");
            } while (v < (unsigned)t);
        }
        __syncwarp();

        const __half* __restrict__ hsrc = g_hh[t % 3];

        // stage this warp's K-slice of h (fp16): 2 commit groups of 16 rows.
        #pragma unroll
        for (int half = 0; half < 2; half++) {
            #pragma unroll
            for (int i = 0; i < 8; i++) {
                int r = half * 16 + i * 2 + (lane >> 4);
                int cch = lane & 15;
                uint32_t so = hb + (uint32_t)((r * 68 + cch * 4) * 4);
                const __half* gp = hsrc + r * HID + kw + cch * 8;
                asm volatile("cp.async.cg.shared.global [%0], [%1], 16;" :: "r"(so), "l"(gp));
            }
            asm volatile("cp.async.commit_group;" ::: "memory");
        }

        float acc[2][4][4];
        #pragma unroll
        for (int mt = 0; mt < 2; mt++)
            #pragma unroll
            for (int nt = 0; nt < 4; nt++)
                #pragma unroll
                for (int r = 0; r < 4; r++) acc[mt][nt][r] = 0.f;

        asm volatile("cp.async.wait_group 1;" ::: "memory");  // rows 0-15 ready
        __syncwarp();
        P2H(0)
        asm volatile("cp.async.wait_group 0;" ::: "memory");  // rows 16-31 ready
        __syncwarp();
        P2H(2)

        // D[r][b] partials -> smem (float2, pad 36)
        #pragma unroll
        for (int mt = 0; mt < 2; mt++) {
            #pragma unroll
            for (int nt = 0; nt < 4; nt++) {
                int r = mt * 16 + g, b = nt * 8 + 2 * tg;
                *(float2*)&red[(w * 32 + r) * 36 + b]     = make_float2(acc[mt][nt][0], acc[mt][nt][1]);
                *(float2*)&red[(w * 32 + r + 8) * 36 + b] = make_float2(acc[mt][nt][2], acc[mt][nt][3]);
            }
        }
        __syncthreads();

        // reduce 8 warps + cell update (thread -> (eb, en)); reads conflict-free
        float si = 0.f, sf = 0.f, sg = 0.f, so = 0.f;
        #pragma unroll
        for (int ww = 0; ww < 8; ww++) {
            si += red[(ww * 32 + en) * 36 + eb];
            sf += red[(ww * 32 + 8 + en) * 36 + eb];
            sg += red[(ww * 32 + 16 + en) * 36 + eb];
            so += red[(ww * 32 + 24 + en) * 36 + eb];
        }
        float gi = sigm(si + xi);
        float gf = sigm(sf + xf);
        float gg = ftanh(sg + xgt);
        float go = sigm(so + xo);
        c = gf * c + gi * gg;
        float h = go * ftanh(c);

        g_hh[(t + 1) % 3][eb * HID + n0 + en] = __float2half(h);
        if (t == TT - 1) out[eb * HID + n0 + en] = h;

        // publish: all 256 h stores done -> one release store of this CTA's flag
        __syncthreads();
        if (tid == 0) {
            asm volatile("st.release.gpu.global.u32 [%0], %1;"
                         :: "l"(g_flag + blockIdx.x * 64), "r"((unsigned)(t + 1)) : "memory");
        }
    }
}

// ---------------- launch ----------------
extern "C" void kernel_launch(void* const* d_in, const int* in_sizes, int n_in,
                              void* d_out, int out_size) {
    const float* x   = (const float*)d_in[0];
    const float* wih = (const float*)d_in[1];
    const float* whh = (const float*)d_in[2];
    const float* bih = (const float*)d_in[3];
    const float* bhh = (const float*)d_in[4];
    float* out = (float*)d_out;

    cudaFuncSetAttribute(k_gemm,  cudaFuncAttributeMaxDynamicSharedMemorySize, 55296);
    cudaFuncSetAttribute(k_recur, cudaFuncAttributeMaxDynamicSharedMemorySize, 106496);

    k_prep<<<20480, 256>>>((const float4*)x, (const float4*)wih);
    k_init<<<128, 256>>>();

    dim3 gg(128, 64);
    k_gemm<<<gg, 256, 55296>>>(bih, bhh);
    k_recur<<<NCTA, 256, 106496>>>(whh, out);
}

// round 17
// speedup vs baseline: 1.5667x; 1.0457x over previous
#include <cuda_runtime.h>
#include <cuda_fp16.h>
#include <cstdint>
#include <cstddef>

#define HID   1024
#define NG    4096
#define BATCH 32
#define TT    512
#define NCTA  128

// ---------------- device scratch (allocation-free) ----------------
__device__ float  g_xg[(size_t)TT * BATCH * NG];   // [t*32+b][4H] precomputed input gates (fp32)
__device__ __half g_xh[(size_t)TT * BATCH * HID];  // x, fp16, row m = t*32+b
__device__ __half g_wh[(size_t)NG * HID];          // w_ih, fp16
__device__ __half g_hh[3][BATCH * HID];            // triple-buffered hidden state (fp16)
__device__ unsigned g_flag[NCTA * 64];             // per-producer epoch flags, 256B apart

// ---------------- helpers ----------------
// fp16 mma, fp32 accumulate
__device__ __forceinline__ void mma16(float* d, const unsigned* a, unsigned b0, unsigned b1) {
    asm volatile(
        "mma.sync.aligned.m16n8k16.row.col.f32.f16.f16.f32 "
        "{%0,%1,%2,%3}, {%4,%5,%6,%7}, {%8,%9}, {%0,%1,%2,%3};\n"
        : "+f"(d[0]), "+f"(d[1]), "+f"(d[2]), "+f"(d[3])
        : "r"(a[0]), "r"(a[1]), "r"(a[2]), "r"(a[3]), "r"(b0), "r"(b1));
}

__device__ __forceinline__ unsigned packh(float lo, float hi) {
    __half2 h = __floats2half2_rn(lo, hi);
    return *(unsigned*)&h;
}

__device__ __forceinline__ float sigm(float x) {
    float e = __expf(-x);
    return __fdividef(1.f, 1.f + e);     // rcp(inf)=0 -> saturates correctly
}

// saturating fast tanh: 1 - 2/(e^{2x}+1); NaN-free at +-inf
__device__ __forceinline__ float ftanh(float x) {
    float e = __expf(2.f * x);
    return 1.f - __fdividef(2.f, e + 1.f);
}

// ---------------- fused prep: convert to fp16; reorder x rows to m = t*32+b ----------------
__global__ void k_prep(const float4* __restrict__ x, const float4* __restrict__ w) {
    if (blockIdx.x < 16384) {
        size_t i = (size_t)blockIdx.x * 256 + threadIdx.x;  // over 4,194,304 float4
        int hq  = (int)(i & 255);
        int row = (int)(i >> 8);       // = b*512 + t
        int b   = row >> 9;
        int t   = row & 511;
        float4 v = x[i];
        uint2 p = make_uint2(packh(v.x, v.y), packh(v.z, v.w));
        ((uint2*)g_xh)[(size_t)(t * 32 + b) * 256 + hq] = p;
    } else {
        size_t i = (size_t)(blockIdx.x - 16384) * 256 + threadIdx.x;  // over 1,048,576 float4
        float4 v = w[i];
        uint2 p = make_uint2(packh(v.x, v.y), packh(v.z, v.w));
        ((uint2*)g_wh)[i] = p;
    }
}

// fused init: zero h buffer 0 + reset all flags
__global__ void k_init() {
    int i = blockIdx.x * 256 + threadIdx.x;   // 128 x 256 = 32768
    g_hh[0][i] = __float2half(0.f);
    if (i < NCTA * 64) g_flag[i] = 0u;
}

// ---------------- Phase 1: xg = x' @ w_ih^T + b_ih + b_hh (fp16 mma) ----------------
// M=16384 (m = t*32+b), N=4096, K=1024. BM=128, BN=128, BK=64 halves, 256 thr.
// Warp grid 2x4: warp tile 64x32 (mt 0..3, nt 0..3). 2 CTAs/SM.
// smem words: A[2][128][36] then B[2][128][36] (row = 64 halves pad to 72
// => stride 36 words; frag LDS bank = 4g+tg+8ks -> conflict-free). 73728 B.
// Per k-iter: 4 mma-k steps of 16. 16 iterations total.

__device__ __forceinline__ void p1_load(uint32_t sb, int s, int m0, int n0, int k0, int tid) {
    #pragma unroll
    for (int i = 0; i < 4; i++) {
        int ch = tid + i * 256;                // 1024 chunks: 128 rows x 8
        int row = ch >> 3, cq = ch & 7;
        uint32_t so = sb + (uint32_t)((s * 4608 + row * 36 + cq * 4) * 4);
        const __half* gp = g_xh + (size_t)(m0 + row) * HID + k0 + cq * 8;
        asm volatile("cp.async.cg.shared.global [%0], [%1], 16;" :: "r"(so), "l"(gp));
    }
    #pragma unroll
    for (int i = 0; i < 4; i++) {
        int ch = tid + i * 256;                // 1024 chunks: 128 rows x 8
        int row = ch >> 3, cq = ch & 7;
        uint32_t so = sb + (uint32_t)((9216 + s * 4608 + row * 36 + cq * 4) * 4);
        const __half* gp = g_wh + (size_t)(n0 + row) * HID + k0 + cq * 8;
        asm volatile("cp.async.cg.shared.global [%0], [%1], 16;" :: "r"(so), "l"(gp));
    }
    asm volatile("cp.async.commit_group;" ::: "memory");
}

__global__ void __launch_bounds__(256, 2) k_gemm(const float* __restrict__ bih,
                                                 const float* __restrict__ bhh) {
    extern __shared__ float sm[];
    const int tid  = threadIdx.x;
    const int lane = tid & 31, w = tid >> 5;
    const int wm = w >> 2, wn = w & 3;          // 2 x 4 warp grid
    const int g = lane >> 2, tg = lane & 3;
    const int m0 = blockIdx.x * 128;
    const int n0 = blockIdx.y * 128;
    uint32_t sb = (uint32_t)__cvta_generic_to_shared(sm);

    float acc[4][4][4];
    #pragma unroll
    for (int mt = 0; mt < 4; mt++)
        #pragma unroll
        for (int nt = 0; nt < 4; nt++)
            #pragma unroll
            for (int r = 0; r < 4; r++) acc[mt][nt][r] = 0.f;

    p1_load(sb, 0, m0, n0, 0, tid);
    int s = 0;
    for (int it = 0; it < 16; ++it) {
        if (it + 1 < 16) p1_load(sb, s ^ 1, m0, n0, (it + 1) * 64, tid);
        else asm volatile("cp.async.commit_group;" ::: "memory");
        asm volatile("cp.async.wait_group 1;" ::: "memory");
        __syncthreads();

        const unsigned* A = (const unsigned*)(sm + s * 4608);
        const unsigned* B = (const unsigned*)(sm + 9216 + s * 4608);
        #pragma unroll
        for (int ks = 0; ks < 4; ks++) {
            int col = ks * 8 + tg;
            unsigned a[4][4], bf[4][2];
            #pragma unroll
            for (int mt = 0; mt < 4; mt++) {
                int r = wm * 64 + mt * 16 + g;
                a[mt][0] = A[r * 36 + col];
                a[mt][1] = A[(r + 8) * 36 + col];
                a[mt][2] = A[r * 36 + col + 4];
                a[mt][3] = A[(r + 8) * 36 + col + 4];
            }
            #pragma unroll
            for (int nt = 0; nt < 4; nt++) {
                int r = wn * 32 + nt * 8 + g;
                bf[nt][0] = B[r * 36 + col];
                bf[nt][1] = B[r * 36 + col + 4];
            }
            #pragma unroll
            for (int mt = 0; mt < 4; mt++)
                #pragma unroll
                for (int nt = 0; nt < 4; nt++)
                    mma16(acc[mt][nt], a[mt], bf[nt][0], bf[nt][1]);
        }
        __syncthreads();
        s ^= 1;
    }

    // epilogue: add biases, store to g_xg[m][n] (fp32)
    #pragma unroll
    for (int mt = 0; mt < 4; mt++) {
        #pragma unroll
        for (int nt = 0; nt < 4; nt++) {
            int n = n0 + wn * 32 + nt * 8 + 2 * tg;
            float b0 = bih[n] + bhh[n];
            float b1 = bih[n + 1] + bhh[n + 1];
            int ma = m0 + wm * 64 + mt * 16 + g;
            float2 v0 = make_float2(acc[mt][nt][0] + b0, acc[mt][nt][1] + b1);
            float2 v1 = make_float2(acc[mt][nt][2] + b0, acc[mt][nt][3] + b1);
            *(float2*)&g_xg[(size_t)ma * NG + n]       = v0;
            *(float2*)&g_xg[(size_t)(ma + 8) * NG + n] = v1;
        }
    }
}

// ---------------- Phase 2: persistent recurrence (fp16 mma, v8) ----------------
// 128 CTAs x 256 threads, 1 CTA/SM. CTA j owns hidden n0=j*8..j*8+7.
// h stored fp16; w_hh fp16 A-fragments in REGISTERS (a[8][2][4]).
// Per-producer epoch flags (no global barrier). Warp w consumes h cols
// [w*128,(w+1)*128), staged warp-privately via cp.async in 4 commit groups of
// 8 batch-rows; mma m16n8k16 runs in four 16-mma blocks, each gated on its
// 8-row group (wait_group 3-q) -> first mma after 2 KB, rest overlapped.
// smem: hbuf 8*32*68 words (69632 B) then red[8][32][36] floats (36864 B).

#define P2H8(nt)                                                            \
    _Pragma("unroll")                                                       \
    for (int ks = 0; ks < 8; ++ks) {                                        \
        int k0 = ks * 8 + tg;                                               \
        unsigned b0 = hwu[((nt) * 8 + g) * 68 + k0];                        \
        unsigned b1 = hwu[((nt) * 8 + g) * 68 + k0 + 4];                    \
        mma16(acc[0][(nt)], a[ks][0], b0, b1);                              \
        mma16(acc[1][(nt)], a[ks][1], b0, b1);                              \
    }

__global__ void __launch_bounds__(256) k_recur(const float* __restrict__ whh,
                                               float* __restrict__ out) {
    extern __shared__ float sm[];
    float* red = sm + 17408;          // after 8 * 2176-word h buffers
    const int tid  = threadIdx.x;
    const int lane = tid & 31, w = tid >> 5;
    const int g = lane >> 2, tg = lane & 3;
    const int n0 = blockIdx.x * 8;
    const int kw = w * 128;           // this warp's hidden (K) slice
    const int j0 = w * 16;            // first producer CTA of this slice
    const int eb = tid >> 3;          // batch index for epilogue
    const int en = tid & 7;           // local hidden index for epilogue

    unsigned* hwu = (unsigned*)sm + w * 2176;  // warp-private h slice (32 x 68 words)
    uint32_t hb = (uint32_t)__cvta_generic_to_shared(hwu);

    // Load this thread's w_hh A-fragments (fp16 pairs) once; resident all steps.
    // local row r = gate*8 + unit -> global row (r>>3)*HID + n0 + (r&7)
    unsigned a[8][2][4];
    #pragma unroll
    for (int ks = 0; ks < 8; ks++) {
        #pragma unroll
        for (int mt = 0; mt < 2; mt++) {
            int r0 = mt * 16 + g;
            int r1 = r0 + 8;
            const float* row0 = whh + (size_t)((r0 >> 3) * HID + n0 + (r0 & 7)) * HID;
            const float* row1 = whh + (size_t)((r1 >> 3) * HID + n0 + (r1 & 7)) * HID;
            int kb = kw + ks * 16 + 2 * tg;
            a[ks][mt][0] = packh(row0[kb],     row0[kb + 1]);
            a[ks][mt][1] = packh(row1[kb],     row1[kb + 1]);
            a[ks][mt][2] = packh(row0[kb + 8], row0[kb + 9]);
            a[ks][mt][3] = packh(row1[kb + 8], row1[kb + 9]);
        }
    }

    float c = 0.f;

    for (int t = 0; t < TT; ++t) {
        // prefetch input-gate values first (independent of flags; hides DRAM lat)
        const float* xp = g_xg + ((size_t)t * 32 + eb) * NG + n0 + en;
        float xi  = __ldcs(xp);
        float xf  = __ldcs(xp + 1024);
        float xgt = __ldcs(xp + 2048);
        float xo  = __ldcs(xp + 3072);

        // wait for this warp's 16 producers to publish h for step t
        if (lane < 16) {
            const unsigned* fp = g_flag + (j0 + lane) * 64;
            unsigned v;
            do {
                asm volatile("ld.acquire.gpu.global.u32 %0, [%1];"
                             : "=r"(v) : "l"(fp) : "memory");
            } while (v < (unsigned)t);
        }
        __syncwarp();

        const __half* __restrict__ hsrc = g_hh[t % 3];

        // stage this warp's K-slice of h (fp16): 4 commit groups of 8 rows.
        #pragma unroll
        for (int q = 0; q < 4; q++) {
            #pragma unroll
            for (int i = 0; i < 4; i++) {
                int r = q * 8 + i * 2 + (lane >> 4);
                int cch = lane & 15;
                uint32_t so = hb + (uint32_t)((r * 68 + cch * 4) * 4);
                const __half* gp = hsrc + r * HID + kw + cch * 8;
                asm volatile("cp.async.cg.shared.global [%0], [%1], 16;" :: "r"(so), "l"(gp));
            }
            asm volatile("cp.async.commit_group;" ::: "memory");
        }

        float acc[2][4][4];
        #pragma unroll
        for (int mt = 0; mt < 2; mt++)
            #pragma unroll
            for (int nt = 0; nt < 4; nt++)
                #pragma unroll
                for (int r = 0; r < 4; r++) acc[mt][nt][r] = 0.f;

        asm volatile("cp.async.wait_group 3;" ::: "memory");
        __syncwarp();
        P2H8(0)
        asm volatile("cp.async.wait_group 2;" ::: "memory");
        __syncwarp();
        P2H8(1)
        asm volatile("cp.async.wait_group 1;" ::: "memory");
        __syncwarp();
        P2H8(2)
        asm volatile("cp.async.wait_group 0;" ::: "memory");
        __syncwarp();
        P2H8(3)

        // D[r][b] partials -> smem (float2, pad 36)
        #pragma unroll
        for (int mt = 0; mt < 2; mt++) {
            #pragma unroll
            for (int nt = 0; nt < 4; nt++) {
                int r = mt * 16 + g, b = nt * 8 + 2 * tg;
                *(float2*)&red[(w * 32 + r) * 36 + b]     = make_float2(acc[mt][nt][0], acc[mt][nt][1]);
                *(float2*)&red[(w * 32 + r + 8) * 36 + b] = make_float2(acc[mt][nt][2], acc[mt][nt][3]);
            }
        }
        __syncthreads();

        // reduce 8 warps + cell update (thread -> (eb, en)); reads conflict-free
        float si = 0.f, sf = 0.f, sg = 0.f, so = 0.f;
        #pragma unroll
        for (int ww = 0; ww < 8; ww++) {
            si += red[(ww * 32 + en) * 36 + eb];
            sf += red[(ww * 32 + 8 + en) * 36 + eb];
            sg += red[(ww * 32 + 16 + en) * 36 + eb];
            so += red[(ww * 32 + 24 + en) * 36 + eb];
        }
        float gi = sigm(si + xi);
        float gf = sigm(sf + xf);
        float gg = ftanh(sg + xgt);
        float go = sigm(so + xo);
        c = gf * c + gi * gg;
        float h = go * ftanh(c);

        g_hh[(t + 1) % 3][eb * HID + n0 + en] = __float2half(h);
        if (t == TT - 1) out[eb * HID + n0 + en] = h;

        // publish: all 256 h stores done -> one release store of this CTA's flag
        __syncthreads();
        if (tid == 0) {
            asm volatile("st.release.gpu.global.u32 [%0], %1;"
                         :: "l"(g_flag + blockIdx.x * 64), "r"((unsigned)(t + 1)) : "memory");
        }
    }
}

// ---------------- launch ----------------
extern "C" void kernel_launch(void* const* d_in, const int* in_sizes, int n_in,
                              void* d_out, int out_size) {
    const float* x   = (const float*)d_in[0];
    const float* wih = (const float*)d_in[1];
    const float* whh = (const float*)d_in[2];
    const float* bih = (const float*)d_in[3];
    const float* bhh = (const float*)d_in[4];
    float* out = (float*)d_out;

    cudaFuncSetAttribute(k_gemm,  cudaFuncAttributeMaxDynamicSharedMemorySize, 73728);
    cudaFuncSetAttribute(k_recur, cudaFuncAttributeMaxDynamicSharedMemorySize, 106496);

    k_prep<<<20480, 256>>>((const float4*)x, (const float4*)wih);
    k_init<<<128, 256>>>();

    dim3 gg(128, 32);
    k_gemm<<<gg, 256, 73728>>>(bih, bhh);
    k_recur<<<NCTA, 256, 106496>>>(whh, out);
}